// round 17
// baseline (speedup 1.0000x reference)
#include <cuda_runtime.h>
#include <cuda_bf16.h>
#include <math.h>
#include <stdint.h>

#define BB 256
#define LL 200
#define DD 512
#define BBDD (BB * DD)
typedef uint32_t u32;
typedef unsigned long long u64t;

// ---------------- fp32 scratch ----------------
__device__ float g_xproj[(size_t)BB * LL * 3 * DD];   // [B,L,3D] (+bih)
__device__ float g_sseq [(size_t)LL * BB * DD];       // [L,B,D]
__device__ float g_rx   [(size_t)LL * BB * DD];
__device__ float g_ux   [(size_t)LL * BB * DD];
__device__ float g_nx   [(size_t)LL * BB * DD];
__device__ float g_u    [BB * DD];
__device__ float g_logits[LL * BB];
__device__ float g_att   [LL * BB];
__device__ float g_zero  [BB * DD];

// ---------------- packed (bf16-pair) activations ----------------
__device__ u32 g_Psess[(size_t)BB * LL * DD];
__device__ u32 g_Ptar [BB * DD];
__device__ u32 g_Psseq[(size_t)LL * BB * DD];

// ---------------- weight fragments (B-operand order) ----------------
__device__ u32 g_Fwih[1536 * DD];
__device__ u32 g_Fwhh[1536 * DD];
__device__ u32 g_Fw  [DD * DD];
__device__ u32 g_Frh [DD * DD];
__device__ u32 g_Fuh [DD * DD];
__device__ u32 g_Fhh [DD * DD];
__device__ u32 g_Frx [DD * DD];
__device__ u32 g_Fux [DD * DD];
__device__ u32 g_Fhx [DD * DD];

__device__ __forceinline__ float sigf(float x) { return 1.0f / (1.0f + __expf(-x)); }

__device__ __forceinline__ u32 packbf(float x) {
    __nv_bfloat16 hi = __float2bfloat16(x);
    float hf = __bfloat162float(hi);
    __nv_bfloat16 lo = __float2bfloat16(x - hf);
    return (u32)__bfloat16_as_ushort(hi) | ((u32)__bfloat16_as_ushort(lo) << 16);
}

__device__ __forceinline__ void pf2(const void* p) {
    asm volatile("prefetch.global.L2 [%0];" :: "l"(p));
}

__device__ __forceinline__ u32 smaddr(const void* p) {
    return (u32)__cvta_generic_to_shared(p);
}
__device__ __forceinline__ u32 mapa_u32(u32 a, int rank) {
    u32 r;
    asm("mapa.shared::cluster.u32 %0, %1, %2;" : "=r"(r) : "r"(a), "r"(rank));
    return r;
}
__device__ __forceinline__ void st_cl_u64(u32 a, u64t v) {
    asm volatile("st.shared::cluster.u64 [%0], %1;" :: "r"(a), "l"(v) : "memory");
}
#define CLUSTER_SYNC() do { \
    asm volatile("barrier.cluster.arrive.aligned;" ::: "memory"); \
    asm volatile("barrier.cluster.wait.aligned;" ::: "memory"); \
} while (0)

__device__ __forceinline__ void mma16(float* d, const u32* a, u32 b0, u32 b1) {
    asm volatile(
        "mma.sync.aligned.m16n8k16.row.col.f32.bf16.bf16.f32 "
        "{%0,%1,%2,%3},{%4,%5,%6,%7},{%8,%9},{%0,%1,%2,%3};"
        : "+f"(d[0]), "+f"(d[1]), "+f"(d[2]), "+f"(d[3])
        : "r"(a[0]), "r"(a[1]), "r"(a[2]), "r"(a[3]), "r"(b0), "r"(b1));
}

// ==================================================================
// 256-thread 128x64 core (unchanged — proven) for the big GEMMs
// ==================================================================
struct MMSmem { u32 A[2][16][136]; };

__device__ __forceinline__ void mm_core(
    MMSmem* sm, const u32* __restrict__ Ap,
    const u32* __restrict__ F, int gnt0,
    float acc[2][4][4])
{
    const int tid  = threadIdx.x;
    const int lane = tid & 31;
    const int gq = lane >> 2, tq = lane & 3;
    const int w  = tid >> 5;
    const int wm = w >> 1, wn = w & 1;
    const int r  = tid >> 1, h = tid & 1;

    const u32* arow = Ap + (size_t)r * DD + h * 8;

    uint4 bv[4], nbv[4], na0, na1;

    uint4 va0 = *(const uint4*)(arow + 0);
    uint4 va1 = *(const uint4*)(arow + 4);
    #pragma unroll
    for (int nt = 0; nt < 4; nt++) {
        int gnt = gnt0 + wn * 4 + nt;
        bv[nt] = *(const uint4*)(F + (((size_t)gnt * 32 + 0) * 32 + lane) * 4);
    }
    {
        u32 e0[4] = {va0.x, va0.y, va0.z, va0.w};
        u32 e1[4] = {va1.x, va1.y, va1.z, va1.w};
        #pragma unroll
        for (int j = 0; j < 4; j++) {
            int jj = (j + 2 * h) & 3;
            sm->A[0][h * 8 + 0 + jj][r] = e0[jj];
            sm->A[0][h * 8 + 4 + jj][r] = e1[jj];
        }
    }
    __syncthreads();

    #pragma unroll 1
    for (int s2 = 0; s2 < 32; s2++) {
        const int buf = s2 & 1;
        if (s2 < 31) {
            const u32* ar = arow + (s2 + 1) * 16;
            na0 = *(const uint4*)(ar);
            na1 = *(const uint4*)(ar + 4);
            #pragma unroll
            for (int nt = 0; nt < 4; nt++) {
                int gnt = gnt0 + wn * 4 + nt;
                nbv[nt] = *(const uint4*)(F + (((size_t)gnt * 32 + (s2 + 1)) * 32 + lane) * 4);
            }
        }
        #pragma unroll
        for (int sl = 0; sl < 2; sl++) {
            u32 a[2][4], as[2][4];
            #pragma unroll
            for (int mt = 0; mt < 2; mt++) {
                int rb = wm * 32 + mt * 16 + gq;
                a[mt][0] = sm->A[buf][sl * 8 + tq][rb];
                a[mt][1] = sm->A[buf][sl * 8 + tq][rb + 8];
                a[mt][2] = sm->A[buf][sl * 8 + tq + 4][rb];
                a[mt][3] = sm->A[buf][sl * 8 + tq + 4][rb + 8];
                #pragma unroll
                for (int q = 0; q < 4; q++)
                    as[mt][q] = __funnelshift_l(a[mt][q], a[mt][q], 16);
            }
            #pragma unroll
            for (int nt = 0; nt < 4; nt++) {
                u32 b0 = sl ? bv[nt].z : bv[nt].x;
                u32 b1 = sl ? bv[nt].w : bv[nt].y;
                #pragma unroll
                for (int mt = 0; mt < 2; mt++) {
                    mma16(acc[mt][nt], a[mt],  b0, b1);
                    mma16(acc[mt][nt], as[mt], b0, b1);
                }
            }
        }
        if (s2 < 31) {
            u32 e0[4] = {na0.x, na0.y, na0.z, na0.w};
            u32 e1[4] = {na1.x, na1.y, na1.z, na1.w};
            #pragma unroll
            for (int j = 0; j < 4; j++) {
                int jj = (j + 2 * h) & 3;
                sm->A[buf ^ 1][h * 8 + 0 + jj][r] = e0[jj];
                sm->A[buf ^ 1][h * 8 + 4 + jj][r] = e1[jj];
            }
            #pragma unroll
            for (int nt = 0; nt < 4; nt++) bv[nt] = nbv[nt];
        }
        __syncthreads();
    }
}

__global__ __launch_bounds__(256) void mm_big(
    const u32* __restrict__ Ap,
    const u32* __restrict__ F,
    const float* __restrict__ bias,
    float* __restrict__ C, int ldc)
{
    __shared__ MMSmem sm;
    const int bm = blockIdx.x * 128, bn = blockIdx.y * 64;
    float acc[2][4][4];
    #pragma unroll
    for (int i = 0; i < 2; i++)
        #pragma unroll
        for (int j = 0; j < 4; j++)
            #pragma unroll
            for (int e = 0; e < 4; e++) acc[i][j][e] = 0.f;
    mm_core(&sm, Ap + (size_t)bm * DD, F, bn >> 3, acc);

    const int lane = threadIdx.x & 31;
    const int gq = lane >> 2, tq = lane & 3;
    const int w = threadIdx.x >> 5;
    const int wm = w >> 1, wn = w & 1;
    #pragma unroll
    for (int mt = 0; mt < 2; mt++)
        #pragma unroll
        for (int nt = 0; nt < 4; nt++) {
            int row = bm + wm * 32 + mt * 16 + gq;
            int col = bn + wn * 32 + nt * 8 + 2 * tq;
            float b0 = bias ? bias[col] : 0.f;
            float b1 = bias ? bias[col + 1] : 0.f;
            *(float2*)(C + (size_t)row * ldc + col) =
                make_float2(acc[mt][nt][0] + b0, acc[mt][nt][1] + b1);
            *(float2*)(C + (size_t)(row + 8) * ldc + col) =
                make_float2(acc[mt][nt][2] + b0, acc[mt][nt][3] + b1);
        }
}

// ==================================================================
// Cluster recurrence GEMM: 16 rows x 64 cols x NG gates, 512 thr,
// A read from LOCAL smem tile [4][16][132] (filled by DSMEM pushes).
// ==================================================================
template<int NG>
__device__ __forceinline__ void rec_gemm(
    const u32* __restrict__ Asm,   // [4][16][132]
    float* Red,
    const u32* const* Fp, const int* gb,
    float acc[NG][2][4])
{
    const int tid  = threadIdx.x;
    const int lane = tid & 31;
    const int gq = lane >> 2, tq = lane & 3;
    const int w  = tid >> 5;
    const int wk = w >> 2;          // k-quarter 0..3
    const int wn = w & 3;           // n-warp 0..3

    uint4 bv[NG][2], nbv[NG][2];
    #pragma unroll
    for (int g = 0; g < NG; g++)
        #pragma unroll
        for (int nt = 0; nt < 2; nt++)
            bv[g][nt] = *(const uint4*)(Fp[g] +
                (((size_t)(gb[g] + wn * 2 + nt) * 32 + wk * 8) * 32 + lane) * 4);

    const u32* arow0 = Asm + (wk * 16 + gq) * 132;
    const u32* arow1 = Asm + (wk * 16 + gq + 8) * 132;

    #pragma unroll 1
    for (int s2 = 0; s2 < 8; s2++) {
        if (s2 < 7) {
            #pragma unroll
            for (int g = 0; g < NG; g++)
                #pragma unroll
                for (int nt = 0; nt < 2; nt++)
                    nbv[g][nt] = *(const uint4*)(Fp[g] +
                        (((size_t)(gb[g] + wn * 2 + nt) * 32 + wk * 8 + s2 + 1) * 32 + lane) * 4);
        }
        #pragma unroll
        for (int sl = 0; sl < 2; sl++) {
            const int kb = s2 * 16 + sl * 8;
            u32 a[4], as[4];
            a[0] = arow0[kb + tq];
            a[1] = arow1[kb + tq];
            a[2] = arow0[kb + tq + 4];
            a[3] = arow1[kb + tq + 4];
            #pragma unroll
            for (int q = 0; q < 4; q++) as[q] = __funnelshift_l(a[q], a[q], 16);
            #pragma unroll
            for (int g = 0; g < NG; g++)
                #pragma unroll
                for (int nt = 0; nt < 2; nt++) {
                    u32 b0 = sl ? bv[g][nt].z : bv[g][nt].x;
                    u32 b1 = sl ? bv[g][nt].w : bv[g][nt].y;
                    mma16(acc[g][nt], a,  b0, b1);
                    mma16(acc[g][nt], as, b0, b1);
                }
        }
        if (s2 < 7) {
            #pragma unroll
            for (int g = 0; g < NG; g++) {
                bv[g][0] = nbv[g][0];
                bv[g][1] = nbv[g][1];
            }
        }
    }

    __syncthreads();

    // reduce wk=1..3 partials into wk=0 (stride NG*8+1: conflict-free)
    const int stride = NG * 8 + 1;
    if (wk) {
        int base = (tid - 128) * stride;
        #pragma unroll
        for (int g = 0; g < NG; g++)
            #pragma unroll
            for (int nt = 0; nt < 2; nt++)
                #pragma unroll
                for (int e = 0; e < 4; e++)
                    Red[base + (g * 2 + nt) * 4 + e] = acc[g][nt][e];
    }
    __syncthreads();
    if (!wk) {
        #pragma unroll
        for (int k = 0; k < 3; k++) {
            int base = (k * 128 + tid) * stride;
            #pragma unroll
            for (int g = 0; g < NG; g++)
                #pragma unroll
                for (int nt = 0; nt < 2; nt++)
                    #pragma unroll
                    for (int e = 0; e < 4; e++)
                        acc[g][nt][e] += Red[base + (g * 2 + nt) * 4 + e];
        }
    }
    __syncthreads();
}

// broadcast own 16x64 packed slice (staged) into all 8 peers' A tile
__device__ __forceinline__ void bcast_slice(
    const u32* Stg, u32* Adst /*[4][16][132] base*/, int di)
{
    const int tid = threadIdx.x;
    const int p = tid >> 6, t64 = tid & 63;
    const int plane = di >> 1, coloff = (di & 1) * 64;
    #pragma unroll
    for (int j = 0; j < 8; j++) {
        int flat = t64 * 8 + j;
        int r = flat >> 5, cr = (flat & 31) * 2;
        u64t v = *(const u64t*)(Stg + r * 66 + cr);
        u32 la = smaddr(Adst + (plane * 16 + r) * 132 + coloff + cr);
        st_cl_u64(mapa_u32(la, p), v);
    }
}

// ---------------- persistent GRU: 16 clusters of 8 ----------------
#define GRU_SMW (16896 + 9600 + 1056)
__global__ __launch_bounds__(512) void gru4(
    const u32* __restrict__ Fwhh, const float* __restrict__ bhh,
    const float* __restrict__ xproj,
    float* __restrict__ sseq, u32* __restrict__ Psseq)
{
    extern __shared__ u32 dyn[];
    u32* Ah = dyn;                        // [2][4][16][132]
    float* Red = (float*)(dyn + 16896);
    u32* Stg = dyn + 16896 + 9600;        // [16][66]

    const int mi = blockIdx.x >> 3, di = blockIdx.x & 7;
    const int bm = mi * 16;
    const int tid = threadIdx.x;
    const int lane = tid & 31;
    const int gq = lane >> 2, tq = lane & 3;
    const int wn_e = (tid >> 5) & 3;

    const u32* Fp[3] = {Fwhh, Fwhh, Fwhh};
    int gb[3] = {di * 8, 64 + di * 8, 128 + di * 8};

    float bh[3][2][2];
    #pragma unroll
    for (int g = 0; g < 3; g++)
        #pragma unroll
        for (int nt = 0; nt < 2; nt++) {
            int col = di * 64 + wn_e * 16 + nt * 8 + 2 * tq;
            bh[g][nt][0] = bhh[g * 512 + col];
            bh[g][nt][1] = bhh[g * 512 + col + 1];
        }

    float hreg[8];
    #pragma unroll
    for (int e = 0; e < 8; e++) hreg[e] = 0.f;

    for (int i = tid; i < 8448; i += 512) Ah[i] = 0;   // h0 = 0 (buf 0)
    __syncthreads();

    for (int l = 0; l < LL; l++) {
        const int buf = l & 1;

        if (tid < 128) {
            int colp = di * 64 + wn_e * 16;
            #pragma unroll
            for (int half = 0; half < 2; half++) {
                int row = bm + gq + half * 8;
                const float* xb = xproj + ((size_t)row * LL + l) * 1536 + colp;
                pf2(xb); pf2(xb + 512); pf2(xb + 1024);
            }
        }

        float acc[3][2][4];
        #pragma unroll
        for (int g = 0; g < 3; g++)
            #pragma unroll
            for (int nt = 0; nt < 2; nt++)
                #pragma unroll
                for (int e = 0; e < 4; e++) acc[g][nt][e] = 0.f;

        rec_gemm<3>(Ah + buf * 8448, Red, Fp, gb, acc);

        if (tid < 128) {
            float* sl_ = sseq + (size_t)l * BBDD;
            u32* pl = Psseq + (size_t)l * BBDD;
            #pragma unroll
            for (int nt = 0; nt < 2; nt++) {
                int col = di * 64 + wn_e * 16 + nt * 8 + 2 * tq;
                #pragma unroll
                for (int half = 0; half < 2; half++) {
                    int row = bm + gq + half * 8;
                    const float* xb = xproj + ((size_t)row * LL + l) * 1536;
                    size_t ix = (size_t)row * DD + col;
                    #pragma unroll
                    for (int c = 0; c < 2; c++) {
                        int e4 = half * 2 + c;
                        int eh = nt * 4 + half * 2 + c;
                        float rr = sigf(xb[col + c] + acc[0][nt][e4] + bh[0][nt][c]);
                        float zz = sigf(xb[512 + col + c] + acc[1][nt][e4] + bh[1][nt][c]);
                        float nn = tanhf(xb[1024 + col + c] + rr * (acc[2][nt][e4] + bh[2][nt][c]));
                        float h0 = hreg[eh];
                        float hn = nn + zz * (h0 - nn);
                        hreg[eh] = hn;
                        sl_[ix + c] = hn;
                        u32 pk = packbf(hn);
                        pl[ix + c] = pk;
                        Stg[(gq + half * 8) * 66 + wn_e * 16 + nt * 8 + 2 * tq + c] = pk;
                    }
                }
            }
        }
        __syncthreads();

        bcast_slice(Stg, Ah + (buf ^ 1) * 8448, di);
        CLUSTER_SYNC();
    }
}

// ---------------- persistent AUGRU: 16 clusters of 8 ----------------
#define AUG_SMW (16896 + 8448 + 9600 + 1056 + 1152)
__global__ __launch_bounds__(512) void augru4(
    const float* __restrict__ hlast, const u32* __restrict__ Pinit,
    const u32* __restrict__ Frh, const u32* __restrict__ Fuh, const u32* __restrict__ Fhh,
    const float* __restrict__ rx, const float* __restrict__ ux, const float* __restrict__ nx,
    const float* __restrict__ att,
    float* __restrict__ out)
{
    extern __shared__ u32 dyn[];
    u32* Ah = dyn;                          // [2][4][16][132]
    u32* Ap = dyn + 16896;                  // [4][16][132]
    float* Red = (float*)(dyn + 25344);
    u32* Stg = dyn + 34944;                 // [16][66]
    float* Ue = (float*)(dyn + 36000);      // [128][9]

    const int mi = blockIdx.x >> 3, di = blockIdx.x & 7;
    const int bm = mi * 16;
    const int tid = threadIdx.x;
    const int lane = tid & 31;
    const int gq = lane >> 2, tq = lane & 3;
    const int wn_e = (tid >> 5) & 3;

    // init: packed h into Ah[0], fp32 h into registers
    if (tid < 256) {
        const int lkq = tid >> 6, lr = (tid >> 2) & 15, lsg = tid & 3;
        const u32* src = Pinit + (size_t)(bm + lr) * DD + lkq * 128 + lsg * 4;
        u32* dst = Ah + (lkq * 16 + lr) * 132 + lsg * 4;
        #pragma unroll
        for (int s = 0; s < 8; s++)
            *(uint4*)(dst + s * 16) = *(const uint4*)(src + s * 16);
    }
    float hreg[8];
    if (tid < 128) {
        #pragma unroll
        for (int nt = 0; nt < 2; nt++) {
            int col = di * 64 + wn_e * 16 + nt * 8 + 2 * tq;
            #pragma unroll
            for (int half = 0; half < 2; half++) {
                int row = bm + gq + half * 8;
                #pragma unroll
                for (int c = 0; c < 2; c++)
                    hreg[nt * 4 + half * 2 + c] = hlast[(size_t)row * DD + col + c];
            }
        }
    }
    __syncthreads();

    for (int l = 0; l < LL; l++) {
        const int buf = l & 1;

        {   // phase A: r and u_eff
            if (tid < 128) {
                int colp = di * 64 + wn_e * 16;
                const float* rxl = rx + (size_t)l * BBDD;
                const float* uxl = ux + (size_t)l * BBDD;
                const float* nxl = nx + (size_t)l * BBDD;
                #pragma unroll
                for (int half = 0; half < 2; half++) {
                    int row = bm + gq + half * 8;
                    size_t ixp = (size_t)row * DD + colp;
                    pf2(rxl + ixp); pf2(uxl + ixp); pf2(nxl + ixp);
                }
                pf2(att + (size_t)l * BB + bm);
            }

            const u32* Fp[2] = {Frh, Fuh};
            int gb[2] = {di * 8, di * 8};
            float acc[2][2][4];
            #pragma unroll
            for (int g = 0; g < 2; g++)
                #pragma unroll
                for (int nt = 0; nt < 2; nt++)
                    #pragma unroll
                    for (int e = 0; e < 4; e++) acc[g][nt][e] = 0.f;

            rec_gemm<2>(Ah + buf * 8448, Red, Fp, gb, acc);

            if (tid < 128) {
                const float* rxl = rx + (size_t)l * BBDD;
                const float* uxl = ux + (size_t)l * BBDD;
                #pragma unroll
                for (int nt = 0; nt < 2; nt++) {
                    int col = di * 64 + wn_e * 16 + nt * 8 + 2 * tq;
                    #pragma unroll
                    for (int half = 0; half < 2; half++) {
                        int row = bm + gq + half * 8;
                        size_t ix = (size_t)row * DD + col;
                        float a = att[(size_t)l * BB + row];
                        #pragma unroll
                        for (int c = 0; c < 2; c++) {
                            int e4 = half * 2 + c;
                            int eh = nt * 4 + half * 2 + c;
                            float vr = acc[0][nt][e4] + rxl[ix + c];
                            float vu = acc[1][nt][e4] + uxl[ix + c];
                            Stg[(gq + half * 8) * 66 + wn_e * 16 + nt * 8 + 2 * tq + c] =
                                packbf(hreg[eh] * sigf(vr));
                            Ue[tid * 9 + eh] = a * sigf(vu);
                        }
                    }
                }
            }
            __syncthreads();
            bcast_slice(Stg, Ap, di);
            CLUSTER_SYNC();
        }

        {   // phase B: hhat + output update
            const u32* Fp[1] = {Fhh};
            int gb[1] = {di * 8};
            float acc[1][2][4];
            #pragma unroll
            for (int nt = 0; nt < 2; nt++)
                #pragma unroll
                for (int e = 0; e < 4; e++) acc[0][nt][e] = 0.f;

            rec_gemm<1>(Ap, Red, Fp, gb, acc);

            if (tid < 128) {
                const float* nxl = nx + (size_t)l * BBDD;
                #pragma unroll
                for (int nt = 0; nt < 2; nt++) {
                    int col = di * 64 + wn_e * 16 + nt * 8 + 2 * tq;
                    #pragma unroll
                    for (int half = 0; half < 2; half++) {
                        int row = bm + gq + half * 8;
                        size_t ix = (size_t)row * DD + col;
                        #pragma unroll
                        for (int c = 0; c < 2; c++) {
                            int e4 = half * 2 + c;
                            int eh = nt * 4 + half * 2 + c;
                            float hh = tanhf(acc[0][nt][e4] + nxl[ix + c]);
                            float h0 = hreg[eh];
                            float u0 = Ue[tid * 9 + eh];
                            float hn = h0 + u0 * (hh - h0);
                            hreg[eh] = hn;
                            if (l == LL - 1)
                                out[ix + c] = hn;
                            else
                                Stg[(gq + half * 8) * 66 + wn_e * 16 + nt * 8 + 2 * tq + c] =
                                    packbf(hn);
                        }
                    }
                }
            }
            __syncthreads();
            if (l < LL - 1) bcast_slice(Stg, Ah + (buf ^ 1) * 8448, di);
            CLUSTER_SYNC();
        }
    }
}

// ---------------- conversion kernels ----------------
__global__ void pack_zero_kernel(const float* __restrict__ x, u32* __restrict__ p, int n4,
                                 float* __restrict__ z, int zn4)
{
    int i = blockIdx.x * 256 + threadIdx.x;
    if (i < n4) {
        float4 v = ((const float4*)x)[i];
        uint4 o;
        o.x = packbf(v.x); o.y = packbf(v.y); o.z = packbf(v.z); o.w = packbf(v.w);
        ((uint4*)p)[i] = o;
    }
    if (i < zn4) ((float4*)z)[i] = make_float4(0.f, 0.f, 0.f, 0.f);
}

__global__ void pack_kernel(const float* __restrict__ x, u32* __restrict__ p, int n4)
{
    int i = blockIdx.x * 256 + threadIdx.x;
    if (i < n4) {
        float4 v = ((const float4*)x)[i];
        uint4 o;
        o.x = packbf(v.x); o.y = packbf(v.y); o.z = packbf(v.z); o.w = packbf(v.w);
        ((uint4*)p)[i] = o;
    }
}

__device__ __forceinline__ void wfrag_one(const float* W, int ldw, int woff,
                                          u32* F, int idx)
{
    int j = idx & 3, lane = (idx >> 2) & 31, s2 = (idx >> 7) & 31, gnt = idx >> 12;
    int g = lane >> 2, t = lane & 3;
    int sl = s2 * 2 + (j >> 1), b = j & 1;
    int ok = sl * 8 + t + 4 * b;
    int n = gnt * 8 + g;
    F[idx] = packbf(W[(size_t)n * ldw + woff + ok]);
}

__global__ void wfrag2_kernel(const float* __restrict__ W1, const float* __restrict__ W2,
                              u32* __restrict__ F1, u32* __restrict__ F2, int total)
{
    int idx0 = blockIdx.x * 256 + threadIdx.x;
    if (idx0 < total)               wfrag_one(W1, DD, 0, F1, idx0);
    else if (idx0 < 2 * total)      wfrag_one(W2, DD, 0, F2, idx0 - total);
}

__global__ void wfrag_kernel(const float* __restrict__ W, int ldw, int woff,
                             u32* __restrict__ F, int total)
{
    int idx = blockIdx.x * 256 + threadIdx.x;
    if (idx < total) wfrag_one(W, ldw, woff, F, idx);
}

// ---------------- attention ----------------
__global__ void attn_logits(const float* __restrict__ s, const float* __restrict__ u,
                            float* __restrict__ logits)
{
    int gw = (blockIdx.x * blockDim.x + threadIdx.x) >> 5;
    int lane = threadIdx.x & 31;
    int b = gw & (BB - 1);
    const float4* sr = (const float4*)(s + (size_t)gw * DD);
    const float4* ur = (const float4*)(u + (size_t)b * DD);
    float acc = 0.f;
    #pragma unroll
    for (int k = lane; k < DD / 4; k += 32) {
        float4 a = sr[k], c = ur[k];
        acc += a.x * c.x + a.y * c.y + a.z * c.z + a.w * c.w;
    }
    #pragma unroll
    for (int o = 16; o > 0; o >>= 1) acc += __shfl_xor_sync(0xffffffffu, acc, o);
    if (lane == 0) logits[gw] = acc;
}

__global__ void attn_softmax(const float* __restrict__ logits, float* __restrict__ att)
{
    int b = blockIdx.x, t = threadIdx.x;
    __shared__ float red[256];
    float v = (t < LL) ? logits[t * BB + b] : -1e30f;
    red[t] = v;
    __syncthreads();
    for (int s = 128; s > 0; s >>= 1) {
        if (t < s) red[t] = fmaxf(red[t], red[t + s]);
        __syncthreads();
    }
    float mx = red[0];
    __syncthreads();
    float e = (t < LL) ? expf(v - mx) : 0.f;
    red[t] = e;
    __syncthreads();
    for (int s = 128; s > 0; s >>= 1) {
        if (t < s) red[t] += red[t + s];
        __syncthreads();
    }
    float inv = 1.f / red[0];
    if (t < LL) att[t * BB + b] = e * inv;
}

// ---------------- host ----------------
extern "C" void kernel_launch(void* const* d_in, const int* in_sizes, int n_in,
                              void* d_out, int out_size)
{
    const float* session  = (const float*)d_in[0];
    const float* target   = (const float*)d_in[1];
    const float* w        = (const float*)d_in[2];
    const float* wih      = (const float*)d_in[3];
    const float* whh      = (const float*)d_in[4];
    const float* bih      = (const float*)d_in[5];
    const float* bhh      = (const float*)d_in[6];
    const float* reset_w  = (const float*)d_in[7];
    const float* reset_b  = (const float*)d_in[8];
    const float* update_w = (const float*)d_in[9];
    const float* update_b = (const float*)d_in[10];
    const float* hhat_w   = (const float*)d_in[11];
    const float* hhat_b   = (const float*)d_in[12];
    float* out = (float*)d_out;

    float *xproj, *sseq, *rx, *ux, *nx, *u, *logits, *att, *zero;
    u32 *Psess, *Ptar, *Psseq;
    u32 *Fwih, *Fwhh, *Fw, *Frh, *Fuh, *Fhh, *Frx, *Fux, *Fhx;

    cudaGetSymbolAddress((void**)&xproj,  g_xproj);
    cudaGetSymbolAddress((void**)&sseq,   g_sseq);
    cudaGetSymbolAddress((void**)&rx,     g_rx);
    cudaGetSymbolAddress((void**)&ux,     g_ux);
    cudaGetSymbolAddress((void**)&nx,     g_nx);
    cudaGetSymbolAddress((void**)&u,      g_u);
    cudaGetSymbolAddress((void**)&logits, g_logits);
    cudaGetSymbolAddress((void**)&att,    g_att);
    cudaGetSymbolAddress((void**)&zero,   g_zero);
    cudaGetSymbolAddress((void**)&Psess,  g_Psess);
    cudaGetSymbolAddress((void**)&Ptar,   g_Ptar);
    cudaGetSymbolAddress((void**)&Psseq,  g_Psseq);
    cudaGetSymbolAddress((void**)&Fwih,   g_Fwih);
    cudaGetSymbolAddress((void**)&Fwhh,   g_Fwhh);
    cudaGetSymbolAddress((void**)&Fw,     g_Fw);
    cudaGetSymbolAddress((void**)&Frh,    g_Frh);
    cudaGetSymbolAddress((void**)&Fuh,    g_Fuh);
    cudaGetSymbolAddress((void**)&Fhh,    g_Fhh);
    cudaGetSymbolAddress((void**)&Frx,    g_Frx);
    cudaGetSymbolAddress((void**)&Fux,    g_Fux);
    cudaGetSymbolAddress((void**)&Fhx,    g_Fhx);

    cudaFuncSetAttribute(gru4,   cudaFuncAttributeMaxDynamicSharedMemorySize, GRU_SMW * 4);
    cudaFuncSetAttribute(augru4, cudaFuncAttributeMaxDynamicSharedMemorySize, AUG_SMW * 4);

    // launch 1: pack session + zero buffer
    pack_zero_kernel<<<(BB * LL * DD / 4 + 255) / 256, 256>>>(
        session, Psess, BB * LL * DD / 4, zero, BB * DD / 4);
    // launch 2: both GRU weight fragment sets
    wfrag2_kernel<<<(2 * 1536 * DD + 255) / 256, 256>>>(wih, whh, Fwih, Fwhh, 1536 * DD);
    // launch 3: x_proj
    {
        dim3 g(BB * LL / 128, 3 * DD / 64);
        mm_big<<<g, 256>>>(Psess, Fwih, bih, xproj, 3 * DD);
    }
    // launch 4: persistent GRU (cluster 8)  <- ncu capture slot
    {
        cudaLaunchConfig_t cfg = {};
        cfg.gridDim = dim3(128, 1, 1);
        cfg.blockDim = dim3(512, 1, 1);
        cfg.dynamicSmemBytes = GRU_SMW * 4;
        cfg.stream = 0;
        cudaLaunchAttribute attr[1];
        attr[0].id = cudaLaunchAttributeClusterDimension;
        attr[0].val.clusterDim.x = 8;
        attr[0].val.clusterDim.y = 1;
        attr[0].val.clusterDim.z = 1;
        cfg.attrs = attr;
        cfg.numAttrs = 1;
        cudaLaunchKernelEx(&cfg, gru4, (const u32*)Fwhh, (const float*)bhh,
                           (const float*)xproj, sseq, Psseq);
    }

    // remaining prep
    pack_kernel<<<(BB * DD / 4 + 255) / 256, 256>>>(target, Ptar, BB * DD / 4);
    wfrag_kernel<<<(DD * DD + 255) / 256, 256>>>(w,        DD,     0,  Fw,  DD * DD);
    wfrag_kernel<<<(DD * DD + 255) / 256, 256>>>(reset_w,  2 * DD, 0,  Frh, DD * DD);
    wfrag_kernel<<<(DD * DD + 255) / 256, 256>>>(update_w, 2 * DD, 0,  Fuh, DD * DD);
    wfrag_kernel<<<(DD * DD + 255) / 256, 256>>>(hhat_w,   2 * DD, 0,  Fhh, DD * DD);
    wfrag_kernel<<<(DD * DD + 255) / 256, 256>>>(reset_w,  2 * DD, DD, Frx, DD * DD);
    wfrag_kernel<<<(DD * DD + 255) / 256, 256>>>(update_w, 2 * DD, DD, Fux, DD * DD);
    wfrag_kernel<<<(DD * DD + 255) / 256, 256>>>(hhat_w,   2 * DD, DD, Fhx, DD * DD);

    // u = target @ w^T
    {
        dim3 g(BB / 128, DD / 64);
        mm_big<<<g, 256>>>(Ptar, Fw, nullptr, u, DD);
    }
    // AUGRU x-projections (biases folded)
    {
        dim3 g(BB * LL / 128, DD / 64);
        mm_big<<<g, 256>>>(Psseq, Frx, reset_b,  rx, DD);
        mm_big<<<g, 256>>>(Psseq, Fux, update_b, ux, DD);
        mm_big<<<g, 256>>>(Psseq, Fhx, hhat_b,   nx, DD);
    }
    // attention
    attn_logits<<<LL * BB / 8, 256>>>(sseq, u, logits);
    attn_softmax<<<BB, 256>>>(logits, att);

    // persistent AUGRU (cluster 8); init h = sseq[L-1]
    {
        cudaLaunchConfig_t cfg = {};
        cfg.gridDim = dim3(128, 1, 1);
        cfg.blockDim = dim3(512, 1, 1);
        cfg.dynamicSmemBytes = AUG_SMW * 4;
        cfg.stream = 0;
        cudaLaunchAttribute attr[1];
        attr[0].id = cudaLaunchAttributeClusterDimension;
        attr[0].val.clusterDim.x = 8;
        attr[0].val.clusterDim.y = 1;
        attr[0].val.clusterDim.z = 1;
        cfg.attrs = attr;
        cfg.numAttrs = 1;
        cudaLaunchKernelEx(&cfg, augru4,
                           (const float*)(sseq + (size_t)(LL - 1) * BBDD),
                           (const u32*)(Psseq + (size_t)(LL - 1) * BBDD),
                           (const u32*)Frh, (const u32*)Fuh, (const u32*)Fhh,
                           (const float*)rx, (const float*)ux, (const float*)nx,
                           (const float*)att, out);
    }
}